// round 3
// baseline (speedup 1.0000x reference)
#include <cuda_runtime.h>
#include <cuda_bf16.h>

// Global accumulators (doubles):
// [0..3]  probsum per class
// [4..7]  intersect per class
// [8..11] count per class
// [12] bce_pos_sum  [13] bce_neg_sum  [14] pos_cnt  [15] neg_cnt
__device__ double g_acc[16];

__global__ void k_init() {
    if (threadIdx.x < 16) g_acc[threadIdx.x] = 0.0;
}

// Block-reduce N float accumulators and atomically add (as double) into g_acc[base..base+N)
template <int N>
__device__ __forceinline__ void block_reduce_add(float* v, int base) {
    #pragma unroll
    for (int i = 0; i < N; i++) {
        #pragma unroll
        for (int off = 16; off > 0; off >>= 1)
            v[i] += __shfl_down_sync(0xffffffffu, v[i], off);
    }
    __shared__ float sm[8 * N];  // up to 8 warps (256 threads)
    const int warp = threadIdx.x >> 5;
    const int lane = threadIdx.x & 31;
    if (lane == 0) {
        #pragma unroll
        for (int i = 0; i < N; i++) sm[warp * N + i] = v[i];
    }
    __syncthreads();
    if (threadIdx.x < N) {
        float t = 0.0f;
        const int nw = blockDim.x >> 5;
        for (int w = 0; w < nw; w++) t += sm[w * N + threadIdx.x];
        atomicAdd(&g_acc[base + threadIdx.x], (double)t);
    }
}

// Soft-dice accumulation: softmax over C=4 channels, per-class sums.
// seg layout: [2, 4, spatial]; mask layout: [2, spatial] (flattened: nvox voxels).
// Processes voxels in groups of 4 via float4/int4 loads (spatial % 4 == 0).
__global__ void k_dice(const float* __restrict__ seg,
                       const int* __restrict__ mask,
                       int spatial, int ngroups) {
    float acc[12];
    #pragma unroll
    for (int i = 0; i < 12; i++) acc[i] = 0.0f;

    const int stride = gridDim.x * blockDim.x;
    for (int g = blockIdx.x * blockDim.x + threadIdx.x; g < ngroups; g += stride) {
        const int v = g * 4;                       // first voxel of group
        const int b = (v >= spatial) ? 1 : 0;      // batch index (n=2)
        const int s = v - b * spatial;
        const float* base = seg + (size_t)b * 4 * spatial + s;

        const float4 x0 = *(const float4*)(base);
        const float4 x1 = *(const float4*)(base + (size_t)spatial);
        const float4 x2 = *(const float4*)(base + 2 * (size_t)spatial);
        const float4 x3 = *(const float4*)(base + 3 * (size_t)spatial);
        const int4  km  = *(const int4*)(mask + v);

        const float a0[4] = {x0.x, x0.y, x0.z, x0.w};
        const float a1[4] = {x1.x, x1.y, x1.z, x1.w};
        const float a2[4] = {x2.x, x2.y, x2.z, x2.w};
        const float a3[4] = {x3.x, x3.y, x3.z, x3.w};
        const int   kk[4] = {km.x, km.y, km.z, km.w};

        #pragma unroll
        for (int j = 0; j < 4; j++) {
            const float c0 = a0[j], c1 = a1[j], c2 = a2[j], c3 = a3[j];
            const float m = fmaxf(fmaxf(c0, c1), fmaxf(c2, c3));
            const float e0 = __expf(c0 - m);
            const float e1 = __expf(c1 - m);
            const float e2 = __expf(c2 - m);
            const float e3 = __expf(c3 - m);
            const float inv = 1.0f / (e0 + e1 + e2 + e3);
            const float p0 = e0 * inv, p1 = e1 * inv, p2 = e2 * inv, p3 = e3 * inv;
            acc[0] += p0; acc[1] += p1; acc[2] += p2; acc[3] += p3;
            const int k = kk[j];
            acc[4]  += (k == 0) ? p0 : 0.0f;
            acc[5]  += (k == 1) ? p1 : 0.0f;
            acc[6]  += (k == 2) ? p2 : 0.0f;
            acc[7]  += (k == 3) ? p3 : 0.0f;
            acc[8]  += (k == 0) ? 1.0f : 0.0f;
            acc[9]  += (k == 1) ? 1.0f : 0.0f;
            acc[10] += (k == 2) ? 1.0f : 0.0f;
            acc[11] += (k == 3) ? 1.0f : 0.0f;
        }
    }
    block_reduce_add<12>(acc, 0);
}

// Weighted BCE accumulation. The per-voxel weight is piecewise-constant by
// target class (neg/sum for t==1, pos/sum for t==0, 0 otherwise), so a single
// pass accumulating class-wise bce sums + counts suffices.
__global__ void k_bce(const float* __restrict__ x,
                      const int* __restrict__ t,
                      int ngroups) {
    float acc[4];  // [0]=bce_pos [1]=bce_neg [2]=pos_cnt [3]=neg_cnt
    #pragma unroll
    for (int i = 0; i < 4; i++) acc[i] = 0.0f;

    const int stride = gridDim.x * blockDim.x;
    for (int g = blockIdx.x * blockDim.x + threadIdx.x; g < ngroups; g += stride) {
        const int v = g * 4;
        const float4 xv = *(const float4*)(x + v);
        const int4   tv = *(const int4*)(t + v);
        const float xa[4] = {xv.x, xv.y, xv.z, xv.w};
        const int   ta[4] = {tv.x, tv.y, tv.z, tv.w};
        #pragma unroll
        for (int j = 0; j < 4; j++) {
            const float xi = xa[j];
            const int   ti = ta[j];
            const float soft = log1pf(__expf(-fabsf(xi)));
            const float mx = fmaxf(xi, 0.0f);
            // bce(t=1) = mx - x + soft ; bce(t=0) = mx + soft
            acc[0] += (ti == 1) ? (mx - xi + soft) : 0.0f;
            acc[1] += (ti == 0) ? (mx + soft) : 0.0f;
            acc[2] += (ti == 1) ? 1.0f : 0.0f;
            acc[3] += (ti == 0) ? 1.0f : 0.0f;
        }
    }
    block_reduce_add<4>(acc, 12);
}

__global__ void k_final(float* __restrict__ out, int edge_elems) {
    const double SMOOTH = 1e-5;
    double dice_sum = 0.0;
    #pragma unroll
    for (int c = 0; c < 4; c++) {
        const double P = g_acc[c];
        const double I = g_acc[4 + c];
        const double K = g_acc[8 + c];
        dice_sum += (2.0 * I + SMOOTH) / (P + K + SMOOTH);
    }
    out[0] = (float)(1.0 - dice_sum / 4.0);

    const double pos = g_acc[14], neg = g_acc[15];
    const double sum = pos + neg;
    const double wsum = (neg / sum) * g_acc[12] + (pos / sum) * g_acc[13];
    out[1] = (float)(wsum / (double)edge_elems);
}

extern "C" void kernel_launch(void* const* d_in, const int* in_sizes, int n_in,
                              void* d_out, int out_size) {
    const float* segin    = (const float*)d_in[0];
    const float* edgein   = (const float*)d_in[1];
    const int*   segmask  = (const int*)d_in[2];
    const int*   edgemask = (const int*)d_in[3];
    float* out = (float*)d_out;

    const int edge_elems = in_sizes[1];   // n * d*h*w  (== total voxel count)
    const int nvox       = in_sizes[2];   // segmask elements == n * d*h*w

    // Problem shape is [2, 4, 96, 160, 160]: n=2 batches, C=4 classes.
    const int n_batch = 2;
    const int sp = nvox / n_batch;        // per-batch spatial size

    const int threads = 256;
    const int blocks  = 1184;             // ~8 CTAs/SM on 148 SMs

    k_init<<<1, 32>>>();
    k_dice<<<blocks, threads>>>(segin, segmask, sp, nvox / 4);
    k_bce<<<blocks, threads>>>(edgein, edgemask, edge_elems / 4);
    k_final<<<1, 1>>>(out, edge_elems);
}